// round 15
// baseline (speedup 1.0000x reference)
#include <cuda_runtime.h>
#include <cuda_fp16.h>
#include <cstdint>
#include <cstddef>

#define T_LEN 16384
#define L_LAB 1024
#define LOG2E 1.4426950408889634f
#define LN2_D 0.6931471805599453
#define CSIZE 16           // cluster size (16 SMs do all the work)
#define TPB   1024
#define ROWS_PER_BLK 64    // L_LAB / CSIZE

// ---- persistent scratch (no allocations allowed) ----
__device__ float  g_alpha[L_LAB];
__device__ double g_csum;
__device__ double g_gold;

static __device__ __forceinline__ float ex2f(float x) {
    float r; asm("ex2.approx.ftz.f32 %0, %1;" : "=f"(r) : "f"(x)); return r;
}
static __device__ __forceinline__ float lg2f_(float x) {
    float r; asm("lg2.approx.f32 %0, %1;" : "=f"(r) : "f"(x)); return r;
}
static __device__ __forceinline__ unsigned smem_u32(const void* p) {
    unsigned a;
    asm("{ .reg .u64 t; cvta.to.shared.u64 t, %1; cvt.u32.u64 %0, t; }"
        : "=r"(a) : "l"(p));
    return a;
}
static __device__ __forceinline__ void st_dsmem64(unsigned localAddr, unsigned peer,
                                                  unsigned long long v) {
    unsigned r;
    asm volatile("mapa.shared::cluster.u32 %0, %1, %2;" : "=r"(r) : "r"(localAddr), "r"(peer));
    asm volatile("st.shared::cluster.b64 [%0], %1;" :: "r"(r), "l"(v) : "memory");
}
// Release-store a 4B flag into CTA `peer`'s smem (same offset as localAddr).
// The release (cluster scope) publishes this warp's prior DSMEM data stores
// (ordered into this lane by the preceding __syncwarp).
static __device__ __forceinline__ void st_flag_release(unsigned localAddr, unsigned peer,
                                                       unsigned v) {
    unsigned r;
    asm volatile("mapa.shared::cluster.u32 %0, %1, %2;" : "=r"(r) : "r"(localAddr), "r"(peer));
    asm volatile("st.release.cluster.shared::cluster.b32 [%0], %1;" :: "r"(r), "r"(v) : "memory");
}
static __device__ __forceinline__ uint4 ldsv4_volatile(unsigned addr) {
    uint4 r;
    asm volatile("ld.volatile.shared.v4.u32 {%0,%1,%2,%3}, [%4];"
                 : "=r"(r.x), "=r"(r.y), "=r"(r.z), "=r"(r.w) : "r"(addr));
    return r;
}
#define CLUSTER_SYNC() do { \
    asm volatile("barrier.cluster.arrive.aligned;" ::: "memory"); \
    asm volatile("barrier.cluster.wait.aligned;"   ::: "memory"); \
} while (0)

static __device__ __forceinline__ float bf16_payload_to_f(unsigned word) {
    return __uint_as_float((word & 0xFFFFu) << 16);
}

// Grid (16, 2), cluster (16,1,1):
//   y==0: the compute cluster (one CTA per SM, 1024 threads).
//   y==1, x==0: gold-path score; other y==1 blocks exit (their cluster never syncs).
__global__ void __launch_bounds__(TPB, 1) __cluster_dims__(CSIZE, 1, 1)
crf_main(const float* __restrict__ pred,
         const int*   __restrict__ ref,
         const float* __restrict__ trans)
{
    if (blockIdx.y == 1) {
        if (blockIdx.x != 0) return;
        __shared__ double red[TPB];
        int tid = threadIdx.x;
        double g = 0.0;
        for (int t = tid; t < T_LEN; t += TPB) {
            int r = __ldg(&ref[t]);
            int p = (t == 0) ? (L_LAB - 2) : __ldg(&ref[t - 1]);
            g += (double)__ldg(&pred[(size_t)t * L_LAB + r])
               + (double)__ldg(&trans[(size_t)r * L_LAB + p]);
        }
        red[tid] = g; __syncthreads();
        for (int s = TPB / 2; s > 0; s >>= 1) {
            if (tid < s) red[tid] += red[tid + s];
            __syncthreads();
        }
        if (tid == 0)
            g_gold = red[0] + (double)__ldg(&trans[(size_t)(L_LAB - 1) * L_LAB + __ldg(&ref[T_LEN - 1])]);
        return;
    }

    // ============ compute cluster (R10 inner; flag-word handoff) ============
    __shared__ __align__(16) float    sAlpha[2][L_LAB]; // exchanged alphas (parity)
    __shared__ __align__(16) __half   sEh[L_LAB];       // e[i] = 2^(alpha[i]-m), fp16
    __shared__ __align__(8)  float    sOut[ROWS_PER_BLK];
    __shared__ __align__(16) unsigned sFlag[2][CSIZE];  // {tag<<16 | bf16(chunkmax)}

    const int tid = threadIdx.x;
    const int w = tid >> 5, l = tid & 31;
    const unsigned rank = blockIdx.x;
    const int jA = (int)rank * ROWS_PER_BLK + 2 * w;    // warp's rows: jA, jA+1

    const unsigned flagBase = smem_u32(&sFlag[0][0]);   // sFlag[b] at flagBase + b*64

    if (tid < 2 * CSIZE) sFlag[tid >> 4][tid & 15] = 0u;

    // ---- precompute expW = exp(W) for rows jA, jA+1, packed fp16.
    // Thread (w,l), chunk k2=0..3 covers labels i = k2*256 + 8l + m, m=0..7.
    __half2 hA[16], hB[16];
    {
        const float* ta = trans + (size_t)jA * L_LAB;
        const float* tb = ta + L_LAB;
        #pragma unroll
        for (int k2 = 0; k2 < 4; ++k2) {
            float4 u = *reinterpret_cast<const float4*>(ta + k2 * 256 + 8 * l);
            float4 v = *reinterpret_cast<const float4*>(ta + k2 * 256 + 8 * l + 4);
            hA[k2 * 4 + 0] = __floats2half2_rn(ex2f(u.x * LOG2E), ex2f(u.y * LOG2E));
            hA[k2 * 4 + 1] = __floats2half2_rn(ex2f(u.z * LOG2E), ex2f(u.w * LOG2E));
            hA[k2 * 4 + 2] = __floats2half2_rn(ex2f(v.x * LOG2E), ex2f(v.y * LOG2E));
            hA[k2 * 4 + 3] = __floats2half2_rn(ex2f(v.z * LOG2E), ex2f(v.w * LOG2E));
            u = *reinterpret_cast<const float4*>(tb + k2 * 256 + 8 * l);
            v = *reinterpret_cast<const float4*>(tb + k2 * 256 + 8 * l + 4);
            hB[k2 * 4 + 0] = __floats2half2_rn(ex2f(u.x * LOG2E), ex2f(u.y * LOG2E));
            hB[k2 * 4 + 1] = __floats2half2_rn(ex2f(u.z * LOG2E), ex2f(u.w * LOG2E));
            hB[k2 * 4 + 2] = __floats2half2_rn(ex2f(v.x * LOG2E), ex2f(v.y * LOG2E));
            hB[k2 * 4 + 3] = __floats2half2_rn(ex2f(v.z * LOG2E), ex2f(v.w * LOG2E));
        }
    }

    // ---- step 1 closed form: alpha2(1)[j] = (W[j,START] + pred[0,j]) * log2e
    float2 fcur, fnext;               // feats (lane 0 only)
    if (l == 0) {
        float wsA = __ldg(&trans[(size_t)jA * L_LAB + (L_LAB - 2)]);
        float wsB = __ldg(&trans[(size_t)(jA + 1) * L_LAB + (L_LAB - 2)]);
        float2 p0 = __ldg(reinterpret_cast<const float2*>(pred + jA));
        sOut[2 * w]     = (wsA + p0.x) * LOG2E;
        sOut[2 * w + 1] = (wsB + p0.y) * LOG2E;
        fcur = __ldg(reinterpret_cast<const float2*>(pred + (size_t)L_LAB + jA));
    }
    __syncthreads();                  // sOut + local flag zeroing complete
    CLUSTER_SYNC();                   // all CTAs' flags zeroed before any push

    // publish step 1: data chunk -> peer w, then release-flag {1, bf16(max)}
    if (w < CSIZE) {
        float2 f = *reinterpret_cast<float2*>(&sOut[2 * l]);
        unsigned long long v;
        asm("mov.b64 %0, {%1,%2};" : "=l"(v) : "f"(f.x), "f"(f.y));
        st_dsmem64(smem_u32(&sAlpha[1][rank * ROWS_PER_BLK + 2 * l]), (unsigned)w, v);
        float mm = fmaxf(sOut[l], sOut[l + 32]);
        #pragma unroll
        for (int o = 16; o > 0; o >>= 1) mm = fmaxf(mm, __shfl_xor_sync(0xffffffffu, mm, o));
        __syncwarp();
        if (l == 0) {
            unsigned bits = (__float_as_uint(mm) + 0x8000u) >> 16;
            st_flag_release(flagBase + 64 + 4 * rank, (unsigned)w, (1u << 16) | (bits & 0xFFFFu));
        }
    }

    double csum = 0.0;

    for (int t = 1; t < T_LEN; ++t) {
        const int buf = t & 1, nbuf = buf ^ 1;

        // ---- local-smem poll: wait for all 16 tagged flags of step t ----
        const unsigned fb = flagBase + (unsigned)buf * 64;
        const unsigned tt = (unsigned)t;
        uint4 f0, f1, f2, f3;
        for (;;) {
            f0 = ldsv4_volatile(fb);
            f1 = ldsv4_volatile(fb + 16);
            f2 = ldsv4_volatile(fb + 32);
            f3 = ldsv4_volatile(fb + 48);
            bool ok = (f0.x >> 16) == tt && (f0.y >> 16) == tt && (f0.z >> 16) == tt && (f0.w >> 16) == tt
                   && (f1.x >> 16) == tt && (f1.y >> 16) == tt && (f1.z >> 16) == tt && (f1.w >> 16) == tt
                   && (f2.x >> 16) == tt && (f2.y >> 16) == tt && (f2.z >> 16) == tt && (f2.w >> 16) == tt
                   && (f3.x >> 16) == tt && (f3.y >> 16) == tt && (f3.z >> 16) == tt && (f3.w >> 16) == tt;
            if (ok) break;
        }
        asm volatile("fence.acq_rel.cluster;" ::: "memory");   // data behind flags visible

        // ---- normalizer m from the 16 bf16 payloads (exact same words on
        // every CTA -> deterministic; m~ >= m - 0.06 keeps fp16 partials safe)
        float m = fmaxf(
            fmaxf(fmaxf(bf16_payload_to_f(f0.x), bf16_payload_to_f(f0.y)),
                  fmaxf(bf16_payload_to_f(f0.z), bf16_payload_to_f(f0.w))),
            fmaxf(fmaxf(bf16_payload_to_f(f1.x), bf16_payload_to_f(f1.y)),
                  fmaxf(bf16_payload_to_f(f1.z), bf16_payload_to_f(f1.w))));
        m = fmaxf(m, fmaxf(
            fmaxf(fmaxf(bf16_payload_to_f(f2.x), bf16_payload_to_f(f2.y)),
                  fmaxf(bf16_payload_to_f(f2.z), bf16_payload_to_f(f2.w))),
            fmaxf(fmaxf(bf16_payload_to_f(f3.x), bf16_payload_to_f(f3.y)),
                  fmaxf(bf16_payload_to_f(f3.z), bf16_payload_to_f(f3.w)))));
        if (rank == 0 && tid == 0) csum += (double)m;

        // e[i] = 2^(alpha[i]-m) <= 2^0.06: fp16 accumulation safe
        sEh[tid] = __float2half_rn(ex2f(sAlpha[buf][tid] - m));
        __syncthreads();

        if (l == 0 && t + 1 < T_LEN)
            fnext = __ldg(reinterpret_cast<const float2*>(pred + (size_t)(t + 1) * L_LAB + jA));

        // ---- rows jA, jA+1: s = sum_i expW[j,i]*e[i], packed half2 HFMA2 ----
        __half2 pA[4], pB[4];
        #pragma unroll
        for (int k2 = 0; k2 < 4; ++k2) {
            uint4 raw = *reinterpret_cast<const uint4*>(&sEh[k2 * 256 + 8 * l]);
            __half2 e0 = *reinterpret_cast<__half2*>(&raw.x);
            __half2 e1 = *reinterpret_cast<__half2*>(&raw.y);
            __half2 e2 = *reinterpret_cast<__half2*>(&raw.z);
            __half2 e3 = *reinterpret_cast<__half2*>(&raw.w);
            __half2 aa = __hmul2(e0, hA[k2 * 4 + 0]);
            aa = __hfma2(e1, hA[k2 * 4 + 1], aa);
            aa = __hfma2(e2, hA[k2 * 4 + 2], aa);
            aa = __hfma2(e3, hA[k2 * 4 + 3], aa);
            pA[k2] = aa;
            __half2 bb = __hmul2(e0, hB[k2 * 4 + 0]);
            bb = __hfma2(e1, hB[k2 * 4 + 1], bb);
            bb = __hfma2(e2, hB[k2 * 4 + 2], bb);
            bb = __hfma2(e3, hB[k2 * 4 + 3], bb);
            pB[k2] = bb;
        }
        __half2 hsA = __hadd2(__hadd2(pA[0], pA[1]), __hadd2(pA[2], pA[3]));
        __half2 hsB = __hadd2(__hadd2(pB[0], pB[1]), __hadd2(pB[2], pB[3]));
        float2 fa = __half22float2(hsA);
        float2 fb2 = __half22float2(hsB);
        float sA = fa.x + fa.y, sB = fb2.x + fb2.y;
        #pragma unroll
        for (int o = 16; o > 0; o >>= 1) {
            sA += __shfl_xor_sync(0xffffffffu, sA, o);
            sB += __shfl_xor_sync(0xffffffffu, sB, o);
        }

        if (l == 0) {
            sOut[2 * w]     = lg2f_(sA) + fcur.x * LOG2E;
            sOut[2 * w + 1] = lg2f_(sB) + fcur.y * LOG2E;
            fcur = fnext;
        }
        __syncthreads();              // sOut complete; sAlpha[buf]/sEh reads done

        // ---- publish step t+1: data push, chunk max (overlaps transit), flag ----
        if (w < CSIZE) {
            float2 f = *reinterpret_cast<float2*>(&sOut[2 * l]);
            unsigned long long vv;
            asm("mov.b64 %0, {%1,%2};" : "=l"(vv) : "f"(f.x), "f"(f.y));
            st_dsmem64(smem_u32(&sAlpha[nbuf][rank * ROWS_PER_BLK + 2 * l]), (unsigned)w, vv);
            float mm = fmaxf(sOut[l], sOut[l + 32]);
            #pragma unroll
            for (int o = 16; o > 0; o >>= 1) mm = fmaxf(mm, __shfl_xor_sync(0xffffffffu, mm, o));
            __syncwarp();             // warp's data stores ordered before the flag
            if (l == 0) {
                unsigned bits = (__float_as_uint(mm) + 0x8000u) >> 16;
                st_flag_release(flagBase + (unsigned)nbuf * 64 + 4 * rank, (unsigned)w,
                                (((unsigned)(t + 1)) << 16) | (bits & 0xFFFFu));
            }
        }
        // No trailing barrier: 2-deep parity induction (a t+2 store/flag needs
        // its producer to consume t+1, which needed OUR t+1 flag, sent after
        // our last reads of that parity's buffers).
    }

    // alpha(T_LEN) sits in parity buffer 0; rank 0 re-polls its flags for tag T_LEN.
    if (rank == 0) {
        const unsigned fb0 = flagBase;
        const unsigned tt = (unsigned)T_LEN;
        for (;;) {
            uint4 f0 = ldsv4_volatile(fb0),      f1 = ldsv4_volatile(fb0 + 16);
            uint4 f2 = ldsv4_volatile(fb0 + 32), f3 = ldsv4_volatile(fb0 + 48);
            bool ok = (f0.x >> 16) == tt && (f0.y >> 16) == tt && (f0.z >> 16) == tt && (f0.w >> 16) == tt
                   && (f1.x >> 16) == tt && (f1.y >> 16) == tt && (f1.z >> 16) == tt && (f1.w >> 16) == tt
                   && (f2.x >> 16) == tt && (f2.y >> 16) == tt && (f2.z >> 16) == tt && (f2.w >> 16) == tt
                   && (f3.x >> 16) == tt && (f3.y >> 16) == tt && (f3.z >> 16) == tt && (f3.w >> 16) == tt;
            if (ok) break;
        }
        asm volatile("fence.acq_rel.cluster;" ::: "memory");
        g_alpha[tid] = sAlpha[0][tid];
        if (tid == 0) g_csum = csum;
    }
    CLUSTER_SYNC();   // no CTA exits while peers' DSMEM stores may be in flight
}

// Terminal: forward = LSE_j(alpha2(T)[j] + W2[STOP,j]) + csum, max-stabilized
// (the STOP row is uniformly -1e4; without the max everything underflows).
__global__ void crf_final(const float* __restrict__ trans, float* __restrict__ out)
{
    __shared__ float  sm[256];
    __shared__ double sd[256];
    int tid = threadIdx.x;

    float x[4];
    float m = -3.4e38f;
    #pragma unroll
    for (int q = 0; q < 4; ++q) {
        int jj = q * 256 + tid;
        float a  = g_alpha[jj];
        float wl = __ldg(&trans[(size_t)(L_LAB - 1) * L_LAB + jj]) * LOG2E;
        x[q] = a + wl;
        m = fmaxf(m, x[q]);
    }
    sm[tid] = m; __syncthreads();
    for (int s = 128; s > 0; s >>= 1) {
        if (tid < s) sm[tid] = fmaxf(sm[tid], sm[tid + s]);
        __syncthreads();
    }
    float M = sm[0];

    double loc = 0.0;
    #pragma unroll
    for (int q = 0; q < 4; ++q) loc += (double)ex2f(x[q] - M);
    sd[tid] = loc; __syncthreads();
    for (int s = 128; s > 0; s >>= 1) {
        if (tid < s) sd[tid] += sd[tid + s];
        __syncthreads();
    }
    if (tid == 0) {
        double fwd = (log2(sd[0]) + (double)M + g_csum) * LN2_D;
        out[0] = (float)(fwd - g_gold);
    }
}

extern "C" void kernel_launch(void* const* d_in, const int* in_sizes, int n_in,
                              void* d_out, int out_size)
{
    const float* pred = nullptr;
    const int*   ref  = nullptr;
    const float* trans = nullptr;
    for (int i = 0; i < n_in; ++i) {
        if (in_sizes[i] == T_LEN)                 ref   = (const int*)d_in[i];
        else if (in_sizes[i] == L_LAB * L_LAB)    trans = (const float*)d_in[i];
        else if (in_sizes[i] == T_LEN * L_LAB)    pred  = (const float*)d_in[i];
    }
    cudaFuncSetAttribute(crf_main, cudaFuncAttributeNonPortableClusterSizeAllowed, 1);

    dim3 grid(CSIZE, 2);
    crf_main<<<grid, TPB>>>(pred, ref, trans);
    crf_final<<<1, 256>>>(trans, (float*)d_out);
}

// round 16
// speedup vs baseline: 1.1669x; 1.1669x over previous
#include <cuda_runtime.h>
#include <cuda_fp16.h>
#include <cstdint>
#include <cstddef>

#define T_LEN 16384
#define L_LAB 1024
#define LOG2E 1.4426950408889634f
#define LN2_D 0.6931471805599453
#define CSIZE 16           // cluster size (16 SMs do all the work)
#define TPB   1024
#define ROWS_PER_BLK 64    // L_LAB / CSIZE

// ---- persistent scratch (no allocations allowed) ----
__device__ float  g_alpha[L_LAB];
__device__ double g_csum;
__device__ double g_gold;

static __device__ __forceinline__ float ex2f(float x) {
    float r; asm("ex2.approx.ftz.f32 %0, %1;" : "=f"(r) : "f"(x)); return r;
}
static __device__ __forceinline__ float lg2f_(float x) {
    float r; asm("lg2.approx.f32 %0, %1;" : "=f"(r) : "f"(x)); return r;
}
static __device__ __forceinline__ unsigned smem_u32(const void* p) {
    unsigned a;
    asm("{ .reg .u64 t; cvta.to.shared.u64 t, %1; cvt.u32.u64 %0, t; }"
        : "=r"(a) : "l"(p));
    return a;
}
static __device__ __forceinline__ void st_dsmem64(unsigned localAddr, unsigned peer,
                                                  unsigned long long v) {
    unsigned r;
    asm volatile("mapa.shared::cluster.u32 %0, %1, %2;" : "=r"(r) : "r"(localAddr), "r"(peer));
    asm volatile("st.shared::cluster.b64 [%0], %1;" :: "r"(r), "l"(v) : "memory");
}
#define CLUSTER_SYNC() do { \
    asm volatile("barrier.cluster.arrive.aligned;" ::: "memory"); \
    asm volatile("barrier.cluster.wait.aligned;"   ::: "memory"); \
} while (0)

// Grid (16, 2), cluster (16,1,1):
//   y==0: the compute cluster (one CTA per SM, 1024 threads).
//   y==1, x==0: gold-path score; other y==1 blocks exit (their cluster never syncs).
__global__ void __launch_bounds__(TPB, 1) __cluster_dims__(CSIZE, 1, 1)
crf_main(const float* __restrict__ pred,
         const int*   __restrict__ ref,
         const float* __restrict__ trans)
{
    if (blockIdx.y == 1) {
        if (blockIdx.x != 0) return;
        __shared__ double red[TPB];
        int tid = threadIdx.x;
        double g = 0.0;
        for (int t = tid; t < T_LEN; t += TPB) {
            int r = __ldg(&ref[t]);
            int p = (t == 0) ? (L_LAB - 2) : __ldg(&ref[t - 1]);
            g += (double)__ldg(&pred[(size_t)t * L_LAB + r])
               + (double)__ldg(&trans[(size_t)r * L_LAB + p]);
        }
        red[tid] = g; __syncthreads();
        for (int s = TPB / 2; s > 0; s >>= 1) {
            if (tid < s) red[tid] += red[tid + s];
            __syncthreads();
        }
        if (tid == 0)
            g_gold = red[0] + (double)__ldg(&trans[(size_t)(L_LAB - 1) * L_LAB + __ldg(&ref[T_LEN - 1])]);
        return;
    }

    // ========== compute cluster (R10 skeleton; 4x16 inner tiling) ==========
    __shared__ __align__(16) float  sAlpha[2][L_LAB];  // exchanged alphas (parity)
    __shared__ __align__(16) __half sEh[L_LAB];        // e[i] = 2^(alpha[i]-m), fp16
    __shared__ __align__(8)  float  sOut[ROWS_PER_BLK];
    __shared__ __align__(16) float  sPartial[128];     // [quad:16][half:2][row:4]
    __shared__ float sRed[40];                         // warp maxima + broadcast slot

    const int tid = threadIdx.x;
    const int w = tid >> 5, l = tid & 31;
    const int q = w >> 1, h = w & 1;                   // row-quad / label-half
    const unsigned rank = blockIdx.x;
    const int rowQ = (int)rank * ROWS_PER_BLK + q * 4; // this warp's 4 rows
    const int labBase = h * 512 + 16 * l;              // this lane's 16 labels

    // ---- precompute expW = exp(W): 4 rows x 16 labels per thread, fp16 packed
    __half2 hW[4][8];
    #pragma unroll
    for (int r = 0; r < 4; ++r) {
        const float* tr = trans + (size_t)(rowQ + r) * L_LAB + labBase;
        #pragma unroll
        for (int cc = 0; cc < 4; ++cc) {
            float4 u = *reinterpret_cast<const float4*>(tr + cc * 4);
            hW[r][cc * 2 + 0] = __floats2half2_rn(ex2f(u.x * LOG2E), ex2f(u.y * LOG2E));
            hW[r][cc * 2 + 1] = __floats2half2_rn(ex2f(u.z * LOG2E), ex2f(u.w * LOG2E));
        }
    }

    // ---- step 1 closed form: alpha2(1)[j] = (W[j,START] + pred[0,j]) * log2e
    // Thread tid<64 owns row rank*64+tid (feats in fcur/fnext).
    float fcur = 0.f, fnext = 0.f;
    if (tid < ROWS_PER_BLK) {
        int j = (int)rank * ROWS_PER_BLK + tid;
        float ws = __ldg(&trans[(size_t)j * L_LAB + (L_LAB - 2)]);
        sOut[tid] = (ws + __ldg(&pred[j])) * LOG2E;
        fcur = __ldg(&pred[(size_t)L_LAB + j]);
    }
    __syncthreads();
    if (w < CSIZE) {                  // warp p pushes this block's chunk to peer p
        float2 f = *reinterpret_cast<float2*>(&sOut[2 * l]);
        unsigned long long v;
        asm("mov.b64 %0, {%1,%2};" : "=l"(v) : "f"(f.x), "f"(f.y));
        st_dsmem64(smem_u32(&sAlpha[1][rank * ROWS_PER_BLK + 2 * l]), (unsigned)w, v);
    }
    CLUSTER_SYNC();

    double csum = 0.0;

    for (int t = 1; t < T_LEN; ++t) {
        const int buf = t & 1, nbuf = buf ^ 1;

        // ---- deterministic block max m (identical data+order on every CTA) ----
        float a = sAlpha[buf][tid];
        float mx = a;
        #pragma unroll
        for (int o = 16; o > 0; o >>= 1) mx = fmaxf(mx, __shfl_xor_sync(0xffffffffu, mx, o));
        if (l == 0) sRed[w] = mx;
        __syncthreads();
        if (tid < 32) {
            float mm = sRed[tid];
            #pragma unroll
            for (int o = 16; o > 0; o >>= 1) mm = fmaxf(mm, __shfl_xor_sync(0xffffffffu, mm, o));
            if (tid == 0) sRed[33] = mm;
        }
        __syncthreads();
        const float m = sRed[33];

        // e[i] = 2^(alpha[i]-m) <= 1  -> fp16 accumulation cannot overflow
        sEh[tid] = __float2half_rn(ex2f(a - m));
        if (rank == 0 && tid == 0) csum += (double)m;
        __syncthreads();

        if (tid < ROWS_PER_BLK && t + 1 < T_LEN)   // coalesced 256B prefetch
            fnext = __ldg(&pred[(size_t)(t + 1) * L_LAB + rank * ROWS_PER_BLK + tid]);

        // ---- inner: 4 rows x 16 labels; ONE 32B e-load per thread ----
        uint4 raw0 = *reinterpret_cast<const uint4*>(&sEh[labBase]);
        uint4 raw1 = *reinterpret_cast<const uint4*>(&sEh[labBase + 8]);
        __half2 e0 = *reinterpret_cast<__half2*>(&raw0.x);
        __half2 e1 = *reinterpret_cast<__half2*>(&raw0.y);
        __half2 e2 = *reinterpret_cast<__half2*>(&raw0.z);
        __half2 e3 = *reinterpret_cast<__half2*>(&raw0.w);
        __half2 e4 = *reinterpret_cast<__half2*>(&raw1.x);
        __half2 e5 = *reinterpret_cast<__half2*>(&raw1.y);
        __half2 e6 = *reinterpret_cast<__half2*>(&raw1.z);
        __half2 e7 = *reinterpret_cast<__half2*>(&raw1.w);

        float p[4];
        #pragma unroll
        for (int r = 0; r < 4; ++r) {
            __half2 acc = __hmul2(e0, hW[r][0]);
            acc = __hfma2(e1, hW[r][1], acc);
            acc = __hfma2(e2, hW[r][2], acc);
            acc = __hfma2(e3, hW[r][3], acc);
            acc = __hfma2(e4, hW[r][4], acc);
            acc = __hfma2(e5, hW[r][5], acc);
            acc = __hfma2(e6, hW[r][6], acc);
            acc = __hfma2(e7, hW[r][7], acc);
            float2 f2 = __half22float2(acc);
            p[r] = f2.x + f2.y;
        }

        // ---- 4 independent standard shfl reduces (interleaved chains) ----
        #pragma unroll
        for (int o = 16; o > 0; o >>= 1) {
            p[0] += __shfl_xor_sync(0xffffffffu, p[0], o);
            p[1] += __shfl_xor_sync(0xffffffffu, p[1], o);
            p[2] += __shfl_xor_sync(0xffffffffu, p[2], o);
            p[3] += __shfl_xor_sync(0xffffffffu, p[3], o);
        }
        if (l == 0)
            *reinterpret_cast<float4*>(&sPartial[(q * 2 + h) * 4]) =
                make_float4(p[0], p[1], p[2], p[3]);
        __syncthreads();

        // ---- combine halves, lg2, feat (one thread per row) ----
        if (tid < ROWS_PER_BLK) {
            int quad = tid >> 2, idx = tid & 3;
            float s = sPartial[(quad * 2) * 4 + idx] + sPartial[(quad * 2 + 1) * 4 + idx];
            sOut[tid] = lg2f_(s) + fcur * LOG2E;
            fcur = fnext;
        }
        __syncthreads();              // sOut complete; sAlpha[buf]/sEh reads done

        // ---- push chunk to every peer (warp p -> peer p), then rendezvous ----
        if (w < CSIZE) {
            float2 f = *reinterpret_cast<float2*>(&sOut[2 * l]);
            unsigned long long vv;
            asm("mov.b64 %0, {%1,%2};" : "=l"(vv) : "f"(f.x), "f"(f.y));
            st_dsmem64(smem_u32(&sAlpha[nbuf][rank * ROWS_PER_BLK + 2 * l]), (unsigned)w, vv);
        }
        CLUSTER_SYNC();               // orders DSMEM stores; doubles as block barrier
    }

    // alpha(T_LEN) sits in parity buffer (T_LEN & 1) == 0
    if (rank == 0) {
        g_alpha[tid] = sAlpha[0][tid];
        if (tid == 0) g_csum = csum;
    }
}

// Terminal: forward = LSE_j(alpha2(T)[j] + W2[STOP,j]) + csum, max-stabilized
// (the STOP row is uniformly -1e4; without the max everything underflows).
__global__ void crf_final(const float* __restrict__ trans, float* __restrict__ out)
{
    __shared__ float  sm[256];
    __shared__ double sd[256];
    int tid = threadIdx.x;

    float x[4];
    float m = -3.4e38f;
    #pragma unroll
    for (int q = 0; q < 4; ++q) {
        int jj = q * 256 + tid;
        float a  = g_alpha[jj];
        float wl = __ldg(&trans[(size_t)(L_LAB - 1) * L_LAB + jj]) * LOG2E;
        x[q] = a + wl;
        m = fmaxf(m, x[q]);
    }
    sm[tid] = m; __syncthreads();
    for (int s = 128; s > 0; s >>= 1) {
        if (tid < s) sm[tid] = fmaxf(sm[tid], sm[tid + s]);
        __syncthreads();
    }
    float M = sm[0];

    double loc = 0.0;
    #pragma unroll
    for (int q = 0; q < 4; ++q) loc += (double)ex2f(x[q] - M);
    sd[tid] = loc; __syncthreads();
    for (int s = 128; s > 0; s >>= 1) {
        if (tid < s) sd[tid] += sd[tid + s];
        __syncthreads();
    }
    if (tid == 0) {
        double fwd = (log2(sd[0]) + (double)M + g_csum) * LN2_D;
        out[0] = (float)(fwd - g_gold);
    }
}

extern "C" void kernel_launch(void* const* d_in, const int* in_sizes, int n_in,
                              void* d_out, int out_size)
{
    const float* pred = nullptr;
    const int*   ref  = nullptr;
    const float* trans = nullptr;
    for (int i = 0; i < n_in; ++i) {
        if (in_sizes[i] == T_LEN)                 ref   = (const int*)d_in[i];
        else if (in_sizes[i] == L_LAB * L_LAB)    trans = (const float*)d_in[i];
        else if (in_sizes[i] == T_LEN * L_LAB)    pred  = (const float*)d_in[i];
    }
    cudaFuncSetAttribute(crf_main, cudaFuncAttributeNonPortableClusterSizeAllowed, 1);

    dim3 grid(CSIZE, 2);
    crf_main<<<grid, TPB>>>(pred, ref, trans);
    crf_final<<<1, 256>>>(trans, (float*)d_out);
}

// round 17
// speedup vs baseline: 1.6751x; 1.4355x over previous
#include <cuda_runtime.h>
#include <cuda_fp16.h>
#include <cstdint>
#include <cstddef>

#define T_LEN 16384
#define L_LAB 1024
#define LOG2E 1.4426950408889634f
#define LN2_D 0.6931471805599453
#define CSIZE 16           // cluster size (16 SMs do all the work)
#define TPB   512          // 16 warps: halve the barrier population vs R10
#define ROWS_PER_BLK 64    // L_LAB / CSIZE

// ---- persistent scratch (no allocations allowed) ----
__device__ float  g_alpha[L_LAB];
__device__ double g_csum;
__device__ double g_gold;

static __device__ __forceinline__ float ex2f(float x) {
    float r; asm("ex2.approx.ftz.f32 %0, %1;" : "=f"(r) : "f"(x)); return r;
}
static __device__ __forceinline__ float lg2f_(float x) {
    float r; asm("lg2.approx.f32 %0, %1;" : "=f"(r) : "f"(x)); return r;
}
static __device__ __forceinline__ unsigned smem_u32(const void* p) {
    unsigned a;
    asm("{ .reg .u64 t; cvta.to.shared.u64 t, %1; cvt.u32.u64 %0, t; }"
        : "=r"(a) : "l"(p));
    return a;
}
static __device__ __forceinline__ void st_dsmem64(unsigned localAddr, unsigned peer,
                                                  unsigned long long v) {
    unsigned r;
    asm volatile("mapa.shared::cluster.u32 %0, %1, %2;" : "=r"(r) : "r"(localAddr), "r"(peer));
    asm volatile("st.shared::cluster.b64 [%0], %1;" :: "r"(r), "l"(v) : "memory");
}
#define CLUSTER_SYNC() do { \
    asm volatile("barrier.cluster.arrive.aligned;" ::: "memory"); \
    asm volatile("barrier.cluster.wait.aligned;"   ::: "memory"); \
} while (0)

// Grid (16, 2), cluster (16,1,1):
//   y==0: the compute cluster (one CTA per SM, 512 threads).
//   y==1, x==0: gold-path score; other y==1 blocks exit (their cluster never syncs).
__global__ void __launch_bounds__(TPB, 1) __cluster_dims__(CSIZE, 1, 1)
crf_main(const float* __restrict__ pred,
         const int*   __restrict__ ref,
         const float* __restrict__ trans)
{
    if (blockIdx.y == 1) {
        if (blockIdx.x != 0) return;
        __shared__ double red[TPB];
        int tid = threadIdx.x;
        double g = 0.0;
        for (int t = tid; t < T_LEN; t += TPB) {
            int r = __ldg(&ref[t]);
            int p = (t == 0) ? (L_LAB - 2) : __ldg(&ref[t - 1]);
            g += (double)__ldg(&pred[(size_t)t * L_LAB + r])
               + (double)__ldg(&trans[(size_t)r * L_LAB + p]);
        }
        red[tid] = g; __syncthreads();
        for (int s = TPB / 2; s > 0; s >>= 1) {
            if (tid < s) red[tid] += red[tid + s];
            __syncthreads();
        }
        if (tid == 0)
            g_gold = red[0] + (double)__ldg(&trans[(size_t)(L_LAB - 1) * L_LAB + __ldg(&ref[T_LEN - 1])]);
        return;
    }

    // ======= compute cluster (R10 skeleton; 16 warps x 4 rows/warp) =======
    __shared__ __align__(16) float  sAlpha[2][L_LAB];  // exchanged alphas (parity)
    __shared__ __align__(16) __half sEh[L_LAB];        // e[i] = 2^(alpha[i]-m), fp16
    __shared__ __align__(16) float  sOut[ROWS_PER_BLK];
    __shared__ __align__(16) float  sRed[CSIZE];       // 16 warp maxima

    const int tid = threadIdx.x;
    const int w = tid >> 5, l = tid & 31;
    const unsigned rank = blockIdx.x;
    const int rowBase = (int)rank * ROWS_PER_BLK + 4 * w;  // warp's 4 rows

    // ---- precompute expW = exp(W): 4 rows x 32 labels per thread, fp16.
    // Lane l covers labels i = k2*256 + 8l + m (k2=0..3, m=0..7) — as R10.
    __half2 hW[4][16];
    #pragma unroll
    for (int r = 0; r < 4; ++r) {
        const float* tr = trans + (size_t)(rowBase + r) * L_LAB;
        #pragma unroll
        for (int k2 = 0; k2 < 4; ++k2) {
            float4 u = *reinterpret_cast<const float4*>(tr + k2 * 256 + 8 * l);
            float4 v = *reinterpret_cast<const float4*>(tr + k2 * 256 + 8 * l + 4);
            hW[r][k2 * 4 + 0] = __floats2half2_rn(ex2f(u.x * LOG2E), ex2f(u.y * LOG2E));
            hW[r][k2 * 4 + 1] = __floats2half2_rn(ex2f(u.z * LOG2E), ex2f(u.w * LOG2E));
            hW[r][k2 * 4 + 2] = __floats2half2_rn(ex2f(v.x * LOG2E), ex2f(v.y * LOG2E));
            hW[r][k2 * 4 + 3] = __floats2half2_rn(ex2f(v.z * LOG2E), ex2f(v.w * LOG2E));
        }
    }

    // ---- step 1 closed form: alpha2(1)[j] = (W[j,START] + pred[0,j]) * log2e
    float4 fcur, fnext;                 // feats for the warp's 4 rows (lane 0 only)
    if (tid < ROWS_PER_BLK) {
        int j = (int)rank * ROWS_PER_BLK + tid;
        float ws = __ldg(&trans[(size_t)j * L_LAB + (L_LAB - 2)]);
        sOut[tid] = (ws + __ldg(&pred[j])) * LOG2E;
    }
    if (l == 0)
        fcur = __ldg(reinterpret_cast<const float4*>(pred + (size_t)L_LAB + rowBase));
    __syncthreads();
    if (w < CSIZE) {                    // warp p pushes this block's chunk to peer p
        float2 f = *reinterpret_cast<float2*>(&sOut[2 * l]);
        unsigned long long v;
        asm("mov.b64 %0, {%1,%2};" : "=l"(v) : "f"(f.x), "f"(f.y));
        st_dsmem64(smem_u32(&sAlpha[1][rank * ROWS_PER_BLK + 2 * l]), (unsigned)w, v);
    }
    CLUSTER_SYNC();

    double csum = 0.0;

    for (int t = 1; t < T_LEN; ++t) {
        const int buf = t & 1, nbuf = buf ^ 1;

        // ---- single-level deterministic max: 16 warp maxima + 15-fmax tree ----
        float a0 = sAlpha[buf][tid];
        float a1 = sAlpha[buf][tid + 512];
        float mx = fmaxf(a0, a1);
        #pragma unroll
        for (int o = 16; o > 0; o >>= 1) mx = fmaxf(mx, __shfl_xor_sync(0xffffffffu, mx, o));
        if (l == 0) sRed[w] = mx;
        __syncthreads();
        float4 r0 = *reinterpret_cast<const float4*>(&sRed[0]);
        float4 r1 = *reinterpret_cast<const float4*>(&sRed[4]);
        float4 r2 = *reinterpret_cast<const float4*>(&sRed[8]);
        float4 r3 = *reinterpret_cast<const float4*>(&sRed[12]);
        float m = fmaxf(fmaxf(fmaxf(r0.x, r0.y), fmaxf(r0.z, r0.w)),
                        fmaxf(fmaxf(r1.x, r1.y), fmaxf(r1.z, r1.w)));
        m = fmaxf(m, fmaxf(fmaxf(fmaxf(r2.x, r2.y), fmaxf(r2.z, r2.w)),
                           fmaxf(fmaxf(r3.x, r3.y), fmaxf(r3.z, r3.w))));
        if (rank == 0 && tid == 0) csum += (double)m;

        // e[i] = 2^(alpha[i]-m) <= 1  -> fp16 accumulation cannot overflow
        sEh[tid]       = __float2half_rn(ex2f(a0 - m));
        sEh[tid + 512] = __float2half_rn(ex2f(a1 - m));
        __syncthreads();

        if (l == 0 && t + 1 < T_LEN)
            fnext = __ldg(reinterpret_cast<const float4*>(
                        pred + (size_t)(t + 1) * L_LAB + rowBase));

        // ---- 4 rows x 32 labels: s_r = sum_i expW[r,i]*e[i], HFMA2 ----
        __half2 acc0, acc1, acc2, acc3;
        {
            uint4 raw = *reinterpret_cast<const uint4*>(&sEh[8 * l]);
            __half2 e0 = *reinterpret_cast<__half2*>(&raw.x);
            __half2 e1 = *reinterpret_cast<__half2*>(&raw.y);
            __half2 e2 = *reinterpret_cast<__half2*>(&raw.z);
            __half2 e3 = *reinterpret_cast<__half2*>(&raw.w);
            acc0 = __hmul2(e0, hW[0][0]);
            acc0 = __hfma2(e1, hW[0][1], acc0);
            acc0 = __hfma2(e2, hW[0][2], acc0);
            acc0 = __hfma2(e3, hW[0][3], acc0);
            acc1 = __hmul2(e0, hW[1][0]);
            acc1 = __hfma2(e1, hW[1][1], acc1);
            acc1 = __hfma2(e2, hW[1][2], acc1);
            acc1 = __hfma2(e3, hW[1][3], acc1);
            acc2 = __hmul2(e0, hW[2][0]);
            acc2 = __hfma2(e1, hW[2][1], acc2);
            acc2 = __hfma2(e2, hW[2][2], acc2);
            acc2 = __hfma2(e3, hW[2][3], acc2);
            acc3 = __hmul2(e0, hW[3][0]);
            acc3 = __hfma2(e1, hW[3][1], acc3);
            acc3 = __hfma2(e2, hW[3][2], acc3);
            acc3 = __hfma2(e3, hW[3][3], acc3);
        }
        #pragma unroll
        for (int k2 = 1; k2 < 4; ++k2) {
            uint4 raw = *reinterpret_cast<const uint4*>(&sEh[k2 * 256 + 8 * l]);
            __half2 e0 = *reinterpret_cast<__half2*>(&raw.x);
            __half2 e1 = *reinterpret_cast<__half2*>(&raw.y);
            __half2 e2 = *reinterpret_cast<__half2*>(&raw.z);
            __half2 e3 = *reinterpret_cast<__half2*>(&raw.w);
            acc0 = __hfma2(e0, hW[0][k2 * 4 + 0], acc0);
            acc0 = __hfma2(e1, hW[0][k2 * 4 + 1], acc0);
            acc0 = __hfma2(e2, hW[0][k2 * 4 + 2], acc0);
            acc0 = __hfma2(e3, hW[0][k2 * 4 + 3], acc0);
            acc1 = __hfma2(e0, hW[1][k2 * 4 + 0], acc1);
            acc1 = __hfma2(e1, hW[1][k2 * 4 + 1], acc1);
            acc1 = __hfma2(e2, hW[1][k2 * 4 + 2], acc1);
            acc1 = __hfma2(e3, hW[1][k2 * 4 + 3], acc1);
            acc2 = __hfma2(e0, hW[2][k2 * 4 + 0], acc2);
            acc2 = __hfma2(e1, hW[2][k2 * 4 + 1], acc2);
            acc2 = __hfma2(e2, hW[2][k2 * 4 + 2], acc2);
            acc2 = __hfma2(e3, hW[2][k2 * 4 + 3], acc2);
            acc3 = __hfma2(e0, hW[3][k2 * 4 + 0], acc3);
            acc3 = __hfma2(e1, hW[3][k2 * 4 + 1], acc3);
            acc3 = __hfma2(e2, hW[3][k2 * 4 + 2], acc3);
            acc3 = __hfma2(e3, hW[3][k2 * 4 + 3], acc3);
        }
        float2 f0 = __half22float2(acc0);
        float2 f1 = __half22float2(acc1);
        float2 f2 = __half22float2(acc2);
        float2 f3 = __half22float2(acc3);
        float p0 = f0.x + f0.y, p1 = f1.x + f1.y, p2 = f2.x + f2.y, p3 = f3.x + f3.y;
        #pragma unroll
        for (int o = 16; o > 0; o >>= 1) {
            p0 += __shfl_xor_sync(0xffffffffu, p0, o);
            p1 += __shfl_xor_sync(0xffffffffu, p1, o);
            p2 += __shfl_xor_sync(0xffffffffu, p2, o);
            p3 += __shfl_xor_sync(0xffffffffu, p3, o);
        }

        if (l == 0) {
            *reinterpret_cast<float4*>(&sOut[4 * w]) =
                make_float4(lg2f_(p0) + fcur.x * LOG2E,
                            lg2f_(p1) + fcur.y * LOG2E,
                            lg2f_(p2) + fcur.z * LOG2E,
                            lg2f_(p3) + fcur.w * LOG2E);
            fcur = fnext;
        }
        __syncthreads();              // sOut complete; sAlpha[buf]/sEh reads done

        // ---- push chunk to every peer (warp p -> peer p), then rendezvous ----
        if (w < CSIZE) {
            float2 f = *reinterpret_cast<float2*>(&sOut[2 * l]);
            unsigned long long vv;
            asm("mov.b64 %0, {%1,%2};" : "=l"(vv) : "f"(f.x), "f"(f.y));
            st_dsmem64(smem_u32(&sAlpha[nbuf][rank * ROWS_PER_BLK + 2 * l]), (unsigned)w, vv);
        }
        CLUSTER_SYNC();               // orders DSMEM stores; doubles as block barrier
    }

    // alpha(T_LEN) sits in parity buffer (T_LEN & 1) == 0
    if (rank == 0) {
        g_alpha[tid]       = sAlpha[0][tid];
        g_alpha[tid + 512] = sAlpha[0][tid + 512];
        if (tid == 0) g_csum = csum;
    }
}

// Terminal: forward = LSE_j(alpha2(T)[j] + W2[STOP,j]) + csum, max-stabilized
// (the STOP row is uniformly -1e4; without the max everything underflows).
__global__ void crf_final(const float* __restrict__ trans, float* __restrict__ out)
{
    __shared__ float  sm[256];
    __shared__ double sd[256];
    int tid = threadIdx.x;

    float x[4];
    float m = -3.4e38f;
    #pragma unroll
    for (int q = 0; q < 4; ++q) {
        int jj = q * 256 + tid;
        float a  = g_alpha[jj];
        float wl = __ldg(&trans[(size_t)(L_LAB - 1) * L_LAB + jj]) * LOG2E;
        x[q] = a + wl;
        m = fmaxf(m, x[q]);
    }
    sm[tid] = m; __syncthreads();
    for (int s = 128; s > 0; s >>= 1) {
        if (tid < s) sm[tid] = fmaxf(sm[tid], sm[tid + s]);
        __syncthreads();
    }
    float M = sm[0];

    double loc = 0.0;
    #pragma unroll
    for (int q = 0; q < 4; ++q) loc += (double)ex2f(x[q] - M);
    sd[tid] = loc; __syncthreads();
    for (int s = 128; s > 0; s >>= 1) {
        if (tid < s) sd[tid] += sd[tid + s];
        __syncthreads();
    }
    if (tid == 0) {
        double fwd = (log2(sd[0]) + (double)M + g_csum) * LN2_D;
        out[0] = (float)(fwd - g_gold);
    }
}

extern "C" void kernel_launch(void* const* d_in, const int* in_sizes, int n_in,
                              void* d_out, int out_size)
{
    const float* pred = nullptr;
    const int*   ref  = nullptr;
    const float* trans = nullptr;
    for (int i = 0; i < n_in; ++i) {
        if (in_sizes[i] == T_LEN)                 ref   = (const int*)d_in[i];
        else if (in_sizes[i] == L_LAB * L_LAB)    trans = (const float*)d_in[i];
        else if (in_sizes[i] == T_LEN * L_LAB)    pred  = (const float*)d_in[i];
    }
    cudaFuncSetAttribute(crf_main, cudaFuncAttributeNonPortableClusterSizeAllowed, 1);

    dim3 grid(CSIZE, 2);
    crf_main<<<grid, TPB>>>(pred, ref, trans);
    crf_final<<<1, 256>>>(trans, (float*)d_out);
}